// round 16
// baseline (speedup 1.0000x reference)
#include <cuda_runtime.h>
#include <cuda_fp16.h>
#include <cstdint>

// ---------------- Problem constants ----------------
#define T_STEPS 512
#define BATCH   256
#define INPUT_  256
#define HID_    64
#define GATES_  256            // 4*HID
#define OUT_    1024
#define M_ROWS  (T_STEPS * BATCH)          // 131072
#define OUT_ELEMS ((size_t)M_ROWS * OUT_)
#define HC_ELEMS  (BATCH * HID_)

// Scratch (allocation-free rule: __device__ globals)
__device__ float  g_xg[(size_t)M_ROWS * GATES_];    // gate pre-activations (fp32)
__device__ __half g_hs_h[(size_t)M_ROWS * HID_];    // hidden states as fp16
__device__ __half g_wih_h[GATES_ * INPUT_];         // W_ih fp16
__device__ __half g_wout_h[OUT_ * HID_];            // W_out fp16

// ---------------- helpers ----------------
__device__ __forceinline__ uint32_t smem_u32(const void* p) {
    uint32_t a;
    asm("{ .reg .u64 t; cvta.to.shared.u64 t, %1; cvt.u32.u64 %0, t; }"
        : "=r"(a) : "l"(p));
    return a;
}
__device__ __forceinline__ float tanh_fast(float x) {
    float y;
    asm("tanh.approx.f32 %0, %1;" : "=f"(y) : "f"(x));
    return y;
}
__device__ __forceinline__ float sigm(float x) {        // recurrence (1 MUFU)
    return 0.5f * tanh_fast(0.5f * x) + 0.5f;
}
__device__ __forceinline__ float sigm_exact(float x) {  // output (2 MUFU, exact)
    return 1.0f / (1.0f + __expf(-x));
}

// Plain-target tensor / async-copy PTX (sm_80+ features only).
#define LDMX4(r, addr) \
    asm volatile("ldmatrix.sync.aligned.m8n8.x4.shared.b16 {%0,%1,%2,%3}, [%4];" \
        : "=r"((r)[0]), "=r"((r)[1]), "=r"((r)[2]), "=r"((r)[3]) : "r"(addr))

#define MMA16816(d, a, b) \
    asm volatile("mma.sync.aligned.m16n8k16.row.col.f32.f16.f16.f32 " \
        "{%0,%1,%2,%3}, {%4,%5,%6,%7}, {%8,%9}, {%0,%1,%2,%3};" \
        : "+f"((d)[0]), "+f"((d)[1]), "+f"((d)[2]), "+f"((d)[3]) \
        : "r"((a)[0]), "r"((a)[1]), "r"((a)[2]), "r"((a)[3]), \
          "r"((b)[0]), "r"((b)[1]))

#define CPA16(dst, src) \
    asm volatile("cp.async.cg.shared.global [%0], [%1], 16;" \
                 :: "r"(dst), "l"(src) : "memory")
#define CPA_COMMIT() asm volatile("cp.async.commit_group;" ::: "memory")
#define CPA_WAIT0()  asm volatile("cp.async.wait_group 0;" ::: "memory")
#define CPA_WAIT1()  asm volatile("cp.async.wait_group 1;" ::: "memory")

// ---------------- f32x2 packed-FMA helpers (LSTM) ----------------
__device__ __forceinline__ unsigned long long pk(float x, float y) {
    unsigned long long r;
    asm("mov.b64 %0, {%1, %2};" : "=l"(r) : "f"(x), "f"(y));
    return r;
}
__device__ __forceinline__ void fma2(unsigned long long& d,
                                     unsigned long long a, unsigned long long b) {
    asm("fma.rn.f32x2 %0, %1, %2, %0;" : "+l"(d) : "l"(a), "l"(b));
}
__device__ __forceinline__ float2 upk(unsigned long long v) {
    float2 r;
    asm("mov.b64 {%0, %1}, %2;" : "=f"(r.x), "=f"(r.y) : "l"(v));
    return r;
}

// ---------------- fp32 -> fp16 weight conversion ----------------
__global__ void __launch_bounds__(256)
k_cvt_h(const float* __restrict__ src, __half* __restrict__ dst, int n8) {
    int i = blockIdx.x * 256 + threadIdx.x;
    if (i >= n8) return;
    size_t idx = (size_t)i * 8;
    float4 a = *(const float4*)(src + idx);
    float4 b = *(const float4*)(src + idx + 4);
    uint4 o;
    __half2* op = (__half2*)&o;
    op[0] = __floats2half2_rn(a.x, a.y);
    op[1] = __floats2half2_rn(a.z, a.w);
    op[2] = __floats2half2_rn(b.x, b.y);
    op[3] = __floats2half2_rn(b.z, b.w);
    *(uint4*)(dst + idx) = o;
}

// ---------------- shared GEMM geometry ----------------
// CTA tile 128x128, BK=32, 8 warps as 2(M) x 4(N); warp tile 64x32.
// Smem tile: 128 rows x 80 B (conflict-free ldmatrix via 20-bank row rotation).
#define SM_LDR 80
#define TILE_B (128 * SM_LDR)
#define XG_SMEM  (4 * TILE_B)   // 2 stages x (A + B)
#define OUT_SMEM (4 * TILE_B)

// MMA block on one stage: 2 x k16, B frags then 4xA-ldmatrix + 4 MMAs
#define MMA_STAGE(aT, bT)                                                       \
    do {                                                                        \
        _Pragma("unroll")                                                       \
        for (int k16 = 0; k16 < 2; k16++) {                                     \
            uint32_t bh[4][2];                                                  \
            _Pragma("unroll")                                                   \
            for (int njp = 0; njp < 2; njp++) {                                 \
                uint32_t th[4];                                                 \
                LDMX4(th, (bT) + boff + njp * (16 * SM_LDR) + k16 * 32);        \
                bh[2 * njp][0] = th[0]; bh[2 * njp][1] = th[1];                 \
                bh[2 * njp + 1][0] = th[2]; bh[2 * njp + 1][1] = th[3];         \
            }                                                                   \
            _Pragma("unroll")                                                   \
            for (int mi = 0; mi < 4; mi++) {                                    \
                uint32_t ah[4];                                                 \
                LDMX4(ah, (aT) + aoff + mi * (16 * SM_LDR) + k16 * 32);         \
                _Pragma("unroll")                                               \
                for (int nj = 0; nj < 4; nj++) MMA16816(acc[mi][nj], ah, bh[nj]); \
            }                                                                   \
        }                                                                       \
    } while (0)

// ---------------- K1: xg = x @ W_ih^T + (b_ih+b_hh) ----------------
// A = x fp32 (converted in-kernel to fp16), B = W_ih fp16 via cp.async.
__global__ void __launch_bounds__(256, 2)
k_xg_mma(const float* __restrict__ x, const float* __restrict__ bih,
         const float* __restrict__ bhh) {
    extern __shared__ char dsm[];
    const uint32_t smBase = smem_u32(dsm);
    constexpr int K = INPUT_;
    const int m0 = blockIdx.y * 128, n0 = blockIdx.x * 128;

    const int tid  = threadIdx.x;
    const int lane = tid & 31;
    const int warp = tid >> 5;
    const int wm = (warp & 1) * 64;
    const int wn = (warp >> 1) * 32;

    float acc[4][4][4];
#pragma unroll
    for (int i = 0; i < 4; i++)
#pragma unroll
        for (int j = 0; j < 4; j++)
#pragma unroll
            for (int q = 0; q < 4; q++) acc[i][j][q] = 0.0f;

    const int lrow = tid >> 1;         // 0..127
    const int lc16 = (tid & 1) * 2;    // 16B-chunk pair {0,1} or {2,3}

    const uint32_t aoff = (uint32_t)((wm + (lane & 15)) * SM_LDR + (lane >> 4) * 16);
    const uint32_t boff = (uint32_t)((wn + (lane & 7) + ((lane >> 4) & 1) * 8) * SM_LDR
                                     + ((lane >> 3) & 1) * 16);

    const __half* Wh = g_wih_h;
    const float*  ap = x + (size_t)(m0 + lrow) * K + lc16 * 8;
    const size_t  brow = (size_t)(n0 + lrow) * K;

    // A regs: 16 fp32 (chunks lc16, lc16+1)
    float4 ar[4];
#define LDA(kt)                                                 \
    do {                                                        \
        ar[0] = *(const float4*)(ap + (kt));                    \
        ar[1] = *(const float4*)(ap + (kt) + 4);                \
        ar[2] = *(const float4*)(ap + (kt) + 8);                \
        ar[3] = *(const float4*)(ap + (kt) + 12);               \
    } while (0)
#define STA(stage)                                                              \
    do {                                                                        \
        _Pragma("unroll")                                                       \
        for (int c = 0; c < 2; c++) {                                           \
            __half2 h[4];                                                       \
            float4 lo = ar[2 * c], hi = ar[2 * c + 1];                          \
            h[0] = __floats2half2_rn(lo.x, lo.y);                               \
            h[1] = __floats2half2_rn(lo.z, lo.w);                               \
            h[2] = __floats2half2_rn(hi.x, hi.y);                               \
            h[3] = __floats2half2_rn(hi.z, hi.w);                               \
            *(uint4*)(dsm + (stage) * (2 * TILE_B) + lrow * SM_LDR              \
                      + (lc16 + c) * 16) = *(uint4*)h;                          \
        }                                                                       \
    } while (0)
#define LDB(stage, kt)                                                          \
    do {                                                                        \
        _Pragma("unroll")                                                       \
        for (int c = 0; c < 2; c++)                                             \
            CPA16(smBase + (stage) * (2 * TILE_B) + TILE_B                      \
                  + lrow * SM_LDR + (lc16 + c) * 16,                            \
                  Wh + brow + (kt) + (lc16 + c) * 8);                           \
    } while (0)

    // Preamble: fill stage 0, prefetch A for kt=32
    LDA(0);
    STA(0);
    LDB(0, 0);
    CPA_COMMIT();
    LDA(32);

    int cur = 0;
    for (int kt = 0; kt < K; kt += 32, cur ^= 1) {
        const bool more = (kt + 32 < K);
        if (more) {
            LDB(cur ^ 1, kt + 32);
            CPA_COMMIT();
            CPA_WAIT1();
        } else {
            CPA_WAIT0();
        }
        __syncthreads();

        const uint32_t aT = smBase + cur * (2 * TILE_B);
        const uint32_t bT = aT + TILE_B;
        MMA_STAGE(aT, bT);

        if (more) {
            STA(cur ^ 1);                  // safe: stage nxt not read until next bar
            if (kt + 64 < K) LDA(kt + 64);
        }
    }
#undef LDA
#undef STA
#undef LDB

    // Epilogue -> g_xg (fp32, no activation)
    const int er = lane >> 2;
    const int ec = (lane & 3) * 2;
#pragma unroll
    for (int nj = 0; nj < 4; nj++) {
        int n = n0 + wn + nj * 8 + ec;
        float bb0 = bih[n]     + bhh[n];
        float bb1 = bih[n + 1] + bhh[n + 1];
#pragma unroll
        for (int mi = 0; mi < 4; mi++) {
            int r0 = m0 + wm + mi * 16 + er;
            *(float2*)(g_xg + (size_t)r0 * GATES_ + n) =
                make_float2(acc[mi][nj][0] + bb0, acc[mi][nj][1] + bb1);
            *(float2*)(g_xg + (size_t)(r0 + 8) * GATES_ + n) =
                make_float2(acc[mi][nj][2] + bb0, acc[mi][nj][3] + bb1);
        }
    }
}

// ---------------- K3: out = sigmoid(hs @ W_out^T + b_out) ----------------
// Both operands fp16 in global (hs written by lstm), cp.async pipeline.
__global__ void __launch_bounds__(256, 2)
k_out_mma(const float* __restrict__ bout, float* __restrict__ out) {
    extern __shared__ char dsm[];
    const uint32_t smBase = smem_u32(dsm);
    constexpr int K = HID_;
    const int m0 = blockIdx.y * 128, n0 = blockIdx.x * 128;

    const int tid  = threadIdx.x;
    const int lane = tid & 31;
    const int warp = tid >> 5;
    const int wm = (warp & 1) * 64;
    const int wn = (warp >> 1) * 32;

    float acc[4][4][4];
#pragma unroll
    for (int i = 0; i < 4; i++)
#pragma unroll
        for (int j = 0; j < 4; j++)
#pragma unroll
            for (int q = 0; q < 4; q++) acc[i][j][q] = 0.0f;

    const int lrow = tid >> 1;
    const int lc16 = (tid & 1) * 2;

    const uint32_t aoff = (uint32_t)((wm + (lane & 15)) * SM_LDR + (lane >> 4) * 16);
    const uint32_t boff = (uint32_t)((wn + (lane & 7) + ((lane >> 4) & 1) * 8) * SM_LDR
                                     + ((lane >> 3) & 1) * 16);

    const __half* A = g_hs_h;
    const __half* B = g_wout_h;
    const size_t arow = (size_t)(m0 + lrow) * K;
    const size_t brow = (size_t)(n0 + lrow) * K;

#define LDAB(stage, kt)                                                         \
    do {                                                                        \
        _Pragma("unroll")                                                       \
        for (int c = 0; c < 2; c++) {                                           \
            uint32_t d = smBase + (stage) * (2 * TILE_B)                        \
                         + lrow * SM_LDR + (lc16 + c) * 16;                     \
            CPA16(d,          A + arow + (kt) + (lc16 + c) * 8);                \
            CPA16(d + TILE_B, B + brow + (kt) + (lc16 + c) * 8);                \
        }                                                                       \
    } while (0)

    LDAB(0, 0);
    CPA_COMMIT();

    int cur = 0;
    for (int kt = 0; kt < K; kt += 32, cur ^= 1) {
        const bool more = (kt + 32 < K);
        if (more) {
            LDAB(cur ^ 1, kt + 32);
            CPA_COMMIT();
            CPA_WAIT1();
        } else {
            CPA_WAIT0();
        }
        __syncthreads();
        const uint32_t aT = smBase + cur * (2 * TILE_B);
        const uint32_t bT = aT + TILE_B;
        MMA_STAGE(aT, bT);
        __syncthreads();
    }
#undef LDAB

    // Epilogue: exact sigmoid (output error dominates harness rel_err)
    const int er = lane >> 2;
    const int ec = (lane & 3) * 2;
#pragma unroll
    for (int nj = 0; nj < 4; nj++) {
        int n = n0 + wn + nj * 8 + ec;
        float bb0 = bout[n];
        float bb1 = bout[n + 1];
#pragma unroll
        for (int mi = 0; mi < 4; mi++) {
            int r0 = m0 + wm + mi * 16 + er;
            *(float2*)(out + (size_t)r0 * OUT_ + n) =
                make_float2(sigm_exact(acc[mi][nj][0] + bb0),
                            sigm_exact(acc[mi][nj][1] + bb1));
            *(float2*)(out + (size_t)(r0 + 8) * OUT_ + n) =
                make_float2(sigm_exact(acc[mi][nj][2] + bb0),
                            sigm_exact(acc[mi][nj][3] + bb1));
        }
    }
}

// ---------------- K2: LSTM recurrence (1 barrier per step) ----------------
// Warp w owns hids j = 8w..8w+7; lane = gate*8 + jj (gate order i,f,g,o).
// Gate exchange via shfl; h double-buffered in smem; hs written as fp16.
__global__ void __launch_bounds__(256, 2)
k_lstm(const float* __restrict__ h0, const float* __restrict__ c0,
       const float* __restrict__ Whh,
       float* __restrict__ hT, float* __restrict__ cT) {
    const int b    = blockIdx.x;
    const int tid  = threadIdx.x;
    const int lane = tid & 31;
    const int w    = tid >> 5;
    const int gate = lane >> 3;
    const int jj   = lane & 7;
    const int j    = w * 8 + jj;
    const int row  = gate * HID_ + j;

    unsigned long long w2[32];
    const float4* wr = (const float4*)(Whh + row * HID_);
#pragma unroll
    for (int q = 0; q < 16; q++) {
        float4 v = wr[q];
        w2[2 * q]     = pk(v.x, v.y);
        w2[2 * q + 1] = pk(v.z, v.w);
    }

    __shared__ __align__(16) float hb[2][HID_];
    if (tid < HID_) hb[0][tid] = h0[b * HID_ + tid];
    float c = c0[b * HID_ + j];
    float h = 0.0f;
    __syncthreads();

    const float* xp = g_xg + (size_t)b * GATES_ + row;
    int p = 0;

#define XLD(tq) (((tq) < T_STEPS) ? xp[(size_t)(tq) * (BATCH * GATES_)] : 0.0f)

#define LSTM_STEP(XV, T)                                                        \
    do {                                                                        \
        unsigned long long a0 = 0, a1 = 0, a2 = 0, a3 = 0;                      \
        const ulonglong2* hp = (const ulonglong2*)hb[p];                        \
        _Pragma("unroll")                                                       \
        for (int q = 0; q < 8; q++) {                                           \
            ulonglong2 hA = hp[2 * q], hB = hp[2 * q + 1];                      \
            fma2(a0, w2[4 * q],     hA.x);                                      \
            fma2(a1, w2[4 * q + 1], hA.y);                                      \
            fma2(a2, w2[4 * q + 2], hB.x);                                      \
            fma2(a3, w2[4 * q + 3], hB.y);                                      \
        }                                                                       \
        float2 s0 = upk(a0), s1 = upk(a1), s2 = upk(a2), s3 = upk(a3);          \
        float s = (XV) + (((s0.x + s0.y) + (s1.x + s1.y)) +                     \
                          ((s2.x + s2.y) + (s3.x + s3.y)));                     \
        float a_ = (gate == 2) ? tanh_fast(s) : sigm(s);                        \
        float i_ = __shfl_sync(0xffffffffu, a_, jj);                            \
        float f_ = __shfl_sync(0xffffffffu, a_, 8 + jj);                        \
        float g_ = __shfl_sync(0xffffffffu, a_, 16 + jj);                       \
        float o_ = __shfl_sync(0xffffffffu, a_, 24 + jj);                       \
        c = f_ * c + i_ * g_;                                                   \
        h = o_ * tanh_fast(c);                                                  \
        if (gate == 0) {                                                        \
            hb[p ^ 1][j] = h;                                                   \
            g_hs_h[((size_t)(T) * BATCH + b) * HID_ + j] = __float2half(h);     \
        }                                                                       \
        __syncthreads();                                                        \
        p ^= 1;                                                                 \
    } while (0)

    float x0 = XLD(0), x1 = XLD(1), x2 = XLD(2), x3 = XLD(3);
    for (int t = 0; t < T_STEPS; t += 4) {
        float n0_ = XLD(t + 4), n1_ = XLD(t + 5), n2_ = XLD(t + 6), n3_ = XLD(t + 7);
        LSTM_STEP(x0, t);
        LSTM_STEP(x1, t + 1);
        LSTM_STEP(x2, t + 2);
        LSTM_STEP(x3, t + 3);
        x0 = n0_; x1 = n1_; x2 = n2_; x3 = n3_;
    }

    if (gate == 0) {
        hT[b * HID_ + j] = h;
        cT[b * HID_ + j] = c;
    }
#undef LSTM_STEP
#undef XLD
}

extern "C" void kernel_launch(void* const* d_in, const int* in_sizes, int n_in,
                              void* d_out, int out_size) {
    const float* x    = (const float*)d_in[0];
    const float* h0   = (const float*)d_in[1];
    const float* c0   = (const float*)d_in[2];
    const float* Wih  = (const float*)d_in[3];
    const float* Whh  = (const float*)d_in[4];
    const float* bih  = (const float*)d_in[5];
    const float* bhh  = (const float*)d_in[6];
    const float* Wout = (const float*)d_in[7];
    const float* bout = (const float*)d_in[8];

    float* out = (float*)d_out;
    float* hT  = out + OUT_ELEMS;
    float* cT  = hT + HC_ELEMS;

    cudaFuncSetAttribute(k_xg_mma, cudaFuncAttributeMaxDynamicSharedMemorySize, XG_SMEM);
    cudaFuncSetAttribute(k_out_mma, cudaFuncAttributeMaxDynamicSharedMemorySize, OUT_SMEM);

    __half *wih_h, *wout_h;
    cudaGetSymbolAddress((void**)&wih_h, g_wih_h);
    cudaGetSymbolAddress((void**)&wout_h, g_wout_h);

    // 0) weight conversions (tiny)
    k_cvt_h<<<(GATES_ * INPUT_ / 8 + 255) / 256, 256>>>(Wih, wih_h, GATES_ * INPUT_ / 8);
    k_cvt_h<<<(OUT_ * HID_ / 8 + 255) / 256, 256>>>(Wout, wout_h, OUT_ * HID_ / 8);

    // 1) xg = x @ W_ih^T + (b_ih + b_hh)  — fused fp32->fp16 A conversion
    k_xg_mma<<<dim3(GATES_ / 128, M_ROWS / 128), 256, XG_SMEM>>>(x, bih, bhh);
    // 2) sequential LSTM recurrence
    k_lstm<<<BATCH, 256>>>(h0, c0, Whh, hT, cT);
    // 3) out = sigmoid(hs @ W_out^T + b_out) — exact output sigmoid
    k_out_mma<<<dim3(OUT_ / 128, M_ROWS / 128), 256, OUT_SMEM>>>(bout, out);
}